// round 1
// baseline (speedup 1.0000x reference)
#include <cuda_runtime.h>
#include <cuda_bf16.h>
#include <math.h>

// ---------------------------------------------------------------------------
// Problem dims (fixed)
// ---------------------------------------------------------------------------
#define T_   2048
#define D_   1024
#define H_   16
#define HD_  64
#define NH_  2
#define STEPS (T_*NH_)          // 4096
#define ROW  (H_*HD_)           // 1024

// ---------------------------------------------------------------------------
// Scratch (static device memory; allocation-free). Padded +1 step for the
// scan's software prefetch (reads one step past the end; values unused).
// ---------------------------------------------------------------------------
__device__ float g_qbuf[(T_ + 1) * ROW];        // x@Wq -> normalized q
__device__ float g_kbuf[(STEPS + 1) * ROW];     // x@Wk -> normalized k
__device__ float g_vbuf[(STEPS + 1) * ROW];     // x@Wv
__device__ float g_gbuf[T_ * ROW];              // x@Wg (raw gate)
__device__ float g_bbuf[T_ * (NH_ * H_)];       // x@Wb raw
__device__ float g_abuf[T_ * H_];               // x@Wa raw
__device__ float g_betab[(STEPS + 1) * H_];     // 2*sigmoid(.)
__device__ float g_decb[(STEPS + 1) * H_];      // exp(g) per step/head
__device__ float g_obuf[T_ * ROW];              // scan output -> gated norm

// ---------------------------------------------------------------------------
// SGEMM: C[M,N] = A[M,K] @ B[K,N], all row-major fp32.
// 128x64 tile, BK=16, 256 threads, 8x4 per-thread microtile.
// M, K assumed multiples of 128/16; N may be small (guarded, multiple of 4).
// ---------------------------------------------------------------------------
#define BM 128
#define BN 64
#define BK 16

__global__ void __launch_bounds__(256) sgemm_kernel(
    const float* __restrict__ A, const float* __restrict__ B,
    float* __restrict__ C, int M, int N, int K)
{
    __shared__ float As[BK][BM + 4];
    __shared__ float Bs[BK][BN];

    const int tid = threadIdx.x;
    const int tx = tid & 15;          // 0..15 -> 4 cols each
    const int ty = tid >> 4;          // 0..15 -> 8 rows each
    const int rowC = blockIdx.y * BM;
    const int colC = blockIdx.x * BN;

    const int rowA = tid >> 2;        // 0..63 (and +64)
    const int kA   = (tid & 3) * 4;
    const int rowB = tid >> 4;        // 0..15
    const int colB = (tid & 15) * 4;

    float acc[8][4];
#pragma unroll
    for (int i = 0; i < 8; i++)
#pragma unroll
        for (int jj = 0; jj < 4; jj++) acc[i][jj] = 0.f;

    for (int k0 = 0; k0 < K; k0 += BK) {
        // Load A tile (128x16)
#pragma unroll
        for (int r = 0; r < 2; r++) {
            int row = rowA + r * 64;
            float4 a = *(const float4*)(A + (size_t)(rowC + row) * K + k0 + kA);
            As[kA + 0][row] = a.x; As[kA + 1][row] = a.y;
            As[kA + 2][row] = a.z; As[kA + 3][row] = a.w;
        }
        // Load B tile (16x64), guarded for small N
        {
            float4 bv = make_float4(0.f, 0.f, 0.f, 0.f);
            if (colC + colB < N)
                bv = *(const float4*)(B + (size_t)(k0 + rowB) * N + colC + colB);
            Bs[rowB][colB + 0] = bv.x; Bs[rowB][colB + 1] = bv.y;
            Bs[rowB][colB + 2] = bv.z; Bs[rowB][colB + 3] = bv.w;
        }
        __syncthreads();

#pragma unroll
        for (int kk = 0; kk < BK; kk++) {
            float4 a0 = *(const float4*)&As[kk][ty * 8];
            float4 a1 = *(const float4*)&As[kk][ty * 8 + 4];
            float4 b0 = *(const float4*)&Bs[kk][tx * 4];
            float a[8] = {a0.x, a0.y, a0.z, a0.w, a1.x, a1.y, a1.z, a1.w};
            float b[4] = {b0.x, b0.y, b0.z, b0.w};
#pragma unroll
            for (int i = 0; i < 8; i++)
#pragma unroll
                for (int jj = 0; jj < 4; jj++)
                    acc[i][jj] = fmaf(a[i], b[jj], acc[i][jj]);
        }
        __syncthreads();
    }

    if (colC + tx * 4 < N) {
#pragma unroll
        for (int i = 0; i < 8; i++) {
            int row = rowC + ty * 8 + i;
            float4 o = make_float4(acc[i][0], acc[i][1], acc[i][2], acc[i][3]);
            *(float4*)(C + (size_t)row * N + colC + tx * 4) = o;
        }
    }
}

// ---------------------------------------------------------------------------
// l2norm rows of 64 (q: scale by HD^-0.5; k: no scale). One warp per row.
// ---------------------------------------------------------------------------
__global__ void prep_norm_kernel()
{
    const int TQ = T_ * H_;            // 32768 q rows
    const int TK = STEPS * H_;         // 65536 k rows
    int w = (blockIdx.x * blockDim.x + threadIdx.x) >> 5;
    int lane = threadIdx.x & 31;
    if (w >= TQ + TK) return;
    float* p;
    float scl;
    if (w < TQ) { p = g_qbuf + (size_t)w * 64; scl = 0.125f; }
    else        { p = g_kbuf + (size_t)(w - TQ) * 64; scl = 1.0f; }
    float x0 = p[lane], x1 = p[lane + 32];
    float ss = x0 * x0 + x1 * x1;
#pragma unroll
    for (int o = 16; o; o >>= 1) ss += __shfl_xor_sync(0xffffffffu, ss, o);
    float rs = rsqrtf(ss + 1e-6f) * scl;
    p[lane] = x0 * rs;
    p[lane + 32] = x1 * rs;
}

// ---------------------------------------------------------------------------
// beta = 2*sigmoid(xWb); dec = exp(-exp(A_log)*softplus(xWa+dt_bias)) at
// sub-step 0, 1.0 at sub-step 1. One thread per (t, nh, h).
// ---------------------------------------------------------------------------
__global__ void prep_scalar_kernel(const float* __restrict__ A_log,
                                   const float* __restrict__ dt_bias)
{
    int i = blockIdx.x * blockDim.x + threadIdx.x;   // < STEPS*H_
    if (i >= STEPS * H_) return;
    int h = i & 15;
    int nh = (i >> 4) & 1;
    int t = i >> 5;
    float br = g_bbuf[i];                 // same layout as [t][nh][h]
    g_betab[i] = 2.0f / (1.0f + expf(-br));
    float d = 1.0f;
    if (nh == 0) {
        float a = g_abuf[t * H_ + h] + dt_bias[h];
        float sp = (a > 20.0f) ? a : log1pf(expf(a));
        d = expf(-expf(A_log[h]) * sp);
    }
    g_decb[i] = d;
}

// ---------------------------------------------------------------------------
// Sequential delta-rule scan. State columns are independent:
// 4 threads per (head h, column v); each owns 16 rows of S in registers.
// pred/o reductions: 2x shfl_xor within the lane quad. 32 blocks x 128 thr.
// Inputs software-pipelined one step ahead (buffers padded +1 step).
// ---------------------------------------------------------------------------
__device__ __forceinline__ void load16(const float* __restrict__ p, float* r)
{
    float4 a = *(const float4*)(p + 0);
    float4 b = *(const float4*)(p + 4);
    float4 c = *(const float4*)(p + 8);
    float4 d = *(const float4*)(p + 12);
    r[0]=a.x; r[1]=a.y; r[2]=a.z; r[3]=a.w;
    r[4]=b.x; r[5]=b.y; r[6]=b.z; r[7]=b.w;
    r[8]=c.x; r[9]=c.y; r[10]=c.z; r[11]=c.w;
    r[12]=d.x; r[13]=d.y; r[14]=d.z; r[15]=d.w;
}

__global__ void __launch_bounds__(128) scan_kernel()
{
    const int h = blockIdx.x >> 1;
    const int tid = threadIdx.x;
    const int vloc = tid >> 2;
    const int j = tid & 3;
    const int v = ((blockIdx.x & 1) << 5) + vloc;

    const float* kp = g_kbuf + h * 64 + j * 16;
    const float* qp = g_qbuf + h * 64 + j * 16;
    const float* vp = g_vbuf + h * 64 + v;
    const float* bp = g_betab + h;
    const float* dp = g_decb + h;
    float* op = g_obuf + h * 64 + v;

    float S[16];
#pragma unroll
    for (int m = 0; m < 16; m++) S[m] = 0.f;

    float kc[16], qc[16];
    float vv, bb, dd;
    load16(kp, kc);
#pragma unroll
    for (int m = 0; m < 16; m++) qc[m] = 0.f;
    vv = vp[0]; bb = bp[0]; dd = dp[0];

#pragma unroll 2
    for (int s = 0; s < STEPS; s++) {
        // prefetch step s+1 (padded buffers make s+1 == STEPS safe)
        float kx[16], qx[16];
        load16(kp + (size_t)(s + 1) * ROW, kx);
        if ((s + 1) & 1) load16(qp + (size_t)((s + 1) >> 1) * ROW, qx);
        else {
#pragma unroll
            for (int m = 0; m < 16; m++) qx[m] = qc[m];
        }
        float vx = vp[(size_t)(s + 1) * ROW];
        float bx = bp[(size_t)(s + 1) * H_];
        float dx = dp[(size_t)(s + 1) * H_];

        // pred = k . S  (4-way split to break FMA chain)
        float p0 = 0.f, p1 = 0.f, p2 = 0.f, p3 = 0.f;
#pragma unroll
        for (int m = 0; m < 4; m++) {
            p0 = fmaf(kc[m +  0], S[m +  0], p0);
            p1 = fmaf(kc[m +  4], S[m +  4], p1);
            p2 = fmaf(kc[m +  8], S[m +  8], p2);
            p3 = fmaf(kc[m + 12], S[m + 12], p3);
        }
        float pred = (p0 + p1) + (p2 + p3);
        pred += __shfl_xor_sync(0xffffffffu, pred, 1);
        pred += __shfl_xor_sync(0xffffffffu, pred, 2);

        float dv = (vv - dd * pred) * bb;
#pragma unroll
        for (int m = 0; m < 16; m++)
            S[m] = fmaf(S[m], dd, kc[m] * dv);

        if (s & 1) {
            float o0 = 0.f, o1 = 0.f, o2 = 0.f, o3 = 0.f;
#pragma unroll
            for (int m = 0; m < 4; m++) {
                o0 = fmaf(qc[m +  0], S[m +  0], o0);
                o1 = fmaf(qc[m +  4], S[m +  4], o1);
                o2 = fmaf(qc[m +  8], S[m +  8], o2);
                o3 = fmaf(qc[m + 12], S[m + 12], o3);
            }
            float o = (o0 + o1) + (o2 + o3);
            o += __shfl_xor_sync(0xffffffffu, o, 1);
            o += __shfl_xor_sync(0xffffffffu, o, 2);
            if (j == 0) op[(size_t)(s >> 1) * ROW] = o;
        }

#pragma unroll
        for (int m = 0; m < 16; m++) { kc[m] = kx[m]; qc[m] = qx[m]; }
        vv = vx; bb = bx; dd = dx;
    }
}

// ---------------------------------------------------------------------------
// Gated RMSNorm + swish gate, in-place on g_obuf. One warp per (t,h) row.
// ---------------------------------------------------------------------------
__global__ void post_kernel(const float* __restrict__ nw)
{
    int w = (blockIdx.x * blockDim.x + threadIdx.x) >> 5;
    int lane = threadIdx.x & 31;
    if (w >= T_ * H_) return;
    float* p = g_obuf + (size_t)w * 64;
    const float* gp = g_gbuf + (size_t)w * 64;
    float x0 = p[lane], x1 = p[lane + 32];
    float ss = x0 * x0 + x1 * x1;
#pragma unroll
    for (int o = 16; o; o >>= 1) ss += __shfl_xor_sync(0xffffffffu, ss, o);
    float rs = rsqrtf(ss * (1.0f / 64.0f) + 1e-5f);
    float g0 = gp[lane], g1 = gp[lane + 32];
    float w0 = nw[lane], w1 = nw[lane + 32];
    float sg0 = g0 / (1.0f + expf(-g0));
    float sg1 = g1 / (1.0f + expf(-g1));
    p[lane]      = x0 * rs * w0 * sg0;
    p[lane + 32] = x1 * rs * w1 * sg1;
}

// ---------------------------------------------------------------------------
// Host launcher
// ---------------------------------------------------------------------------
extern "C" void kernel_launch(void* const* d_in, const int* in_sizes, int n_in,
                              void* d_out, int out_size)
{
    const float* x       = (const float*)d_in[0];
    const float* Wq      = (const float*)d_in[1];
    const float* Wk      = (const float*)d_in[2];
    const float* Wv      = (const float*)d_in[3];
    const float* Wb      = (const float*)d_in[4];
    const float* Wa      = (const float*)d_in[5];
    const float* A_log   = (const float*)d_in[6];
    const float* dt_bias = (const float*)d_in[7];
    const float* Wg      = (const float*)d_in[8];
    const float* nw      = (const float*)d_in[9];
    const float* Wo      = (const float*)d_in[10];
    float* out = (float*)d_out;

    float *qb, *kb, *vb, *gb, *bb, *ab, *ob;
    cudaGetSymbolAddress((void**)&qb, g_qbuf);
    cudaGetSymbolAddress((void**)&kb, g_kbuf);
    cudaGetSymbolAddress((void**)&vb, g_vbuf);
    cudaGetSymbolAddress((void**)&gb, g_gbuf);
    cudaGetSymbolAddress((void**)&bb, g_bbuf);
    cudaGetSymbolAddress((void**)&ab, g_abuf);
    cudaGetSymbolAddress((void**)&ob, g_obuf);

    dim3 blk(256);
    // Projections
    sgemm_kernel<<<dim3(1024 / BN, T_ / BM), blk>>>(x, Wq, qb, T_, 1024, D_);
    sgemm_kernel<<<dim3(2048 / BN, T_ / BM), blk>>>(x, Wk, kb, T_, 2048, D_);
    sgemm_kernel<<<dim3(2048 / BN, T_ / BM), blk>>>(x, Wv, vb, T_, 2048, D_);
    sgemm_kernel<<<dim3(1024 / BN, T_ / BM), blk>>>(x, Wg, gb, T_, 1024, D_);
    sgemm_kernel<<<dim3(1,         T_ / BM), blk>>>(x, Wb, bb, T_, 32,   D_);
    sgemm_kernel<<<dim3(1,         T_ / BM), blk>>>(x, Wa, ab, T_, 16,   D_);

    // Pointwise prep
    {
        int warps = T_ * H_ + STEPS * H_;          // 98304
        prep_norm_kernel<<<(warps + 7) / 8, 256>>>();
        prep_scalar_kernel<<<(STEPS * H_) / 256, 256>>>(A_log, dt_bias);
    }

    // Sequential scan: 32 blocks (2 per head), 128 threads each
    scan_kernel<<<32, 128>>>();

    // Gated RMSNorm + swish
    post_kernel<<<(T_ * H_ + 7) / 8, 256>>>(nw);

    // Output projection
    sgemm_kernel<<<dim3(1024 / BN, T_ / BM), blk>>>(ob, Wo, out, T_, 1024, D_);
}

// round 2
// speedup vs baseline: 1.6820x; 1.6820x over previous
#include <cuda_runtime.h>
#include <cuda_bf16.h>
#include <math.h>

// ---------------------------------------------------------------------------
// Problem dims (fixed)
// ---------------------------------------------------------------------------
#define T_   2048
#define D_   1024
#define H_   16
#define HD_  64
#define NH_  2
#define STEPS (T_*NH_)          // 4096
#define ROW  (H_*HD_)           // 1024
#define SPAD (STEPS + 8)        // padded step count (prefetch overrun)
#define NGRP (STEPS/4)          // 1024 groups of 4 steps

// ---------------------------------------------------------------------------
// Scratch (static device memory; allocation-free). Padded for the scan's
// cp.async prefetch which can read a few steps past the end (values unused).
// ---------------------------------------------------------------------------
__device__ __align__(256) float g_qbuf[(T_ + 4) * ROW];
__device__ __align__(256) float g_kbuf[SPAD * ROW];
__device__ __align__(256) float g_vbuf[SPAD * ROW];
__device__ __align__(256) float g_gbuf[T_ * ROW];
__device__ __align__(256) float g_bbuf[T_ * (NH_ * H_)];
__device__ __align__(256) float g_abuf[T_ * H_];
__device__ __align__(256) float g_betab[H_ * SPAD];     // transposed [h][s]
__device__ __align__(256) float g_decb[H_ * SPAD];      // transposed [h][s]
__device__ __align__(256) float g_obuf[T_ * ROW];

// ---------------------------------------------------------------------------
// f32x2 packed helpers (FFMA2 path: 2x fp32 throughput, PTX-only)
// ---------------------------------------------------------------------------
typedef unsigned long long ull;

__device__ __forceinline__ void fma2(ull& d, ull a, ull b) {
    asm("fma.rn.f32x2 %0, %1, %2, %3;" : "=l"(d) : "l"(a), "l"(b), "l"(d));
}
__device__ __forceinline__ ull pk2(float x, float y) {
    ull r;
    asm("mov.b64 %0, {%1, %2};" : "=l"(r)
        : "r"(__float_as_uint(x)), "r"(__float_as_uint(y)));
    return r;
}
__device__ __forceinline__ void up2(ull v, float& lo, float& hi) {
    unsigned a, b;
    asm("mov.b64 {%0, %1}, %2;" : "=r"(a), "=r"(b) : "l"(v));
    lo = __uint_as_float(a); hi = __uint_as_float(b);
}

// ---------------------------------------------------------------------------
// cp.async helpers
// ---------------------------------------------------------------------------
__device__ __forceinline__ void cpasync16(void* dst, const void* src) {
    unsigned d = (unsigned)__cvta_generic_to_shared(dst);
    asm volatile("cp.async.cg.shared.global [%0], [%1], 16;" :: "r"(d), "l"(src));
}
#define CP_COMMIT() asm volatile("cp.async.commit_group;")
#define CP_WAIT(n)  asm volatile("cp.async.wait_group %0;" :: "n"(n))

// ---------------------------------------------------------------------------
// SGEMM: C[M,N] = A[M,K] @ B[K,N], row-major fp32, FFMA2 inner loop.
// 128x64 tile, BK=16, 256 threads, 8x4 per-thread microtile (as 4 row-pairs).
// ---------------------------------------------------------------------------
#define BM 128
#define BN 64
#define BK 16

__global__ void __launch_bounds__(256) sgemm_kernel(
    const float* __restrict__ A, const float* __restrict__ B,
    float* __restrict__ C, int M, int N, int K)
{
    __shared__ float As[BK][BM + 4];
    __shared__ float Bs[BK][BN];

    const int tid = threadIdx.x;
    const int tx = tid & 15;          // 0..15 -> 4 cols each
    const int ty = tid >> 4;          // 0..15 -> 8 rows each
    const int rowC = blockIdx.y * BM;
    const int colC = blockIdx.x * BN;

    const int rowA = tid >> 2;        // 0..63 (and +64)
    const int kA   = (tid & 3) * 4;
    const int rowB = tid >> 4;        // 0..15
    const int colB = (tid & 15) * 4;

    ull acc2[4][4];                   // [row-pair][col]; lo=row 2r, hi=row 2r+1
#pragma unroll
    for (int r = 0; r < 4; r++)
#pragma unroll
        for (int jj = 0; jj < 4; jj++) acc2[r][jj] = 0ull;

    for (int k0 = 0; k0 < K; k0 += BK) {
#pragma unroll
        for (int r = 0; r < 2; r++) {
            int row = rowA + r * 64;
            float4 a = *(const float4*)(A + (size_t)(rowC + row) * K + k0 + kA);
            As[kA + 0][row] = a.x; As[kA + 1][row] = a.y;
            As[kA + 2][row] = a.z; As[kA + 3][row] = a.w;
        }
        {
            float4 bv = make_float4(0.f, 0.f, 0.f, 0.f);
            if (colC + colB < N)
                bv = *(const float4*)(B + (size_t)(k0 + rowB) * N + colC + colB);
            Bs[rowB][colB + 0] = bv.x; Bs[rowB][colB + 1] = bv.y;
            Bs[rowB][colB + 2] = bv.z; Bs[rowB][colB + 3] = bv.w;
        }
        __syncthreads();

#pragma unroll
        for (int kk = 0; kk < BK; kk++) {
            float4 b0 = *(const float4*)&Bs[kk][tx * 4];
            ull b2[4];
            b2[0] = pk2(b0.x, b0.x); b2[1] = pk2(b0.y, b0.y);
            b2[2] = pk2(b0.z, b0.z); b2[3] = pk2(b0.w, b0.w);
            ull a2[4];
#pragma unroll
            for (int r = 0; r < 4; r++)
                a2[r] = *(const ull*)&As[kk][ty * 8 + 2 * r];
#pragma unroll
            for (int r = 0; r < 4; r++)
#pragma unroll
                for (int jj = 0; jj < 4; jj++)
                    fma2(acc2[r][jj], a2[r], b2[jj]);
        }
        __syncthreads();
    }

    if (colC + tx * 4 < N) {
#pragma unroll
        for (int r = 0; r < 4; r++) {
            float lo[4], hi[4];
#pragma unroll
            for (int jj = 0; jj < 4; jj++) up2(acc2[r][jj], lo[jj], hi[jj]);
            int row0 = rowC + ty * 8 + 2 * r;
            *(float4*)(C + (size_t)row0 * N + colC + tx * 4) =
                make_float4(lo[0], lo[1], lo[2], lo[3]);
            *(float4*)(C + (size_t)(row0 + 1) * N + colC + tx * 4) =
                make_float4(hi[0], hi[1], hi[2], hi[3]);
        }
    }
}

// ---------------------------------------------------------------------------
// l2norm rows of 64 (q: scale by HD^-0.5; k: no scale). One warp per row.
// ---------------------------------------------------------------------------
__global__ void prep_norm_kernel()
{
    const int TQ = T_ * H_;            // 32768 q rows
    const int TK = STEPS * H_;         // 65536 k rows
    int w = (blockIdx.x * blockDim.x + threadIdx.x) >> 5;
    int lane = threadIdx.x & 31;
    if (w >= TQ + TK) return;
    float* p;
    float scl;
    if (w < TQ) { p = g_qbuf + (size_t)w * 64; scl = 0.125f; }
    else        { p = g_kbuf + (size_t)(w - TQ) * 64; scl = 1.0f; }
    float x0 = p[lane], x1 = p[lane + 32];
    float ss = x0 * x0 + x1 * x1;
#pragma unroll
    for (int o = 16; o; o >>= 1) ss += __shfl_xor_sync(0xffffffffu, ss, o);
    float rs = rsqrtf(ss + 1e-6f) * scl;
    p[lane] = x0 * rs;
    p[lane + 32] = x1 * rs;
}

// ---------------------------------------------------------------------------
// beta/dec precompute, written TRANSPOSED [h][s] for contiguous cp.async.
// ---------------------------------------------------------------------------
__global__ void prep_scalar_kernel(const float* __restrict__ A_log,
                                   const float* __restrict__ dt_bias)
{
    int i = blockIdx.x * blockDim.x + threadIdx.x;   // < STEPS*H_
    if (i >= STEPS * H_) return;
    int h = i & 15;
    int nh = (i >> 4) & 1;
    int t = i >> 5;
    int s = t * 2 + nh;
    float br = g_bbuf[i];                 // layout [t][nh][h]
    g_betab[h * SPAD + s] = 2.0f / (1.0f + expf(-br));
    float d = 1.0f;
    if (nh == 0) {
        float a = g_abuf[t * H_ + h] + dt_bias[h];
        float sp = (a > 20.0f) ? a : log1pf(expf(a));
        d = expf(-expf(A_log[h]) * sp);
    }
    g_decb[h * SPAD + s] = d;
}

// ---------------------------------------------------------------------------
// Scan: cp.async smem ring (4 groups x 4 steps), lookahead 2 groups.
// Block = (head, v-half): 32 blocks x 128 threads. 4 threads per column,
// 16 state rows each; pred/o reduced with 2 shfl_xor hops.
// ---------------------------------------------------------------------------
__device__ __forceinline__ void scan_prefetch(
    int gi, int tid,
    const float* kg, const float* qg, const float* vg,
    const float* bg, const float* dg,
    float (*sk)[256], float (*sq)[128], float (*sv)[128], float (*sb)[8])
{
    int slot = gi & 3;
    int s0 = gi * 4; if (s0 > STEPS) s0 = STEPS;
    int t0 = s0 >> 1;
    if (tid < 64) {
        int si = tid >> 4, off = (tid & 15) * 4;
        cpasync16(&sk[slot][si * 64 + off], kg + (size_t)(s0 + si) * ROW + off);
    } else if (tid < 96) {
        int c = tid - 64; int ti = c >> 4, off = (c & 15) * 4;
        cpasync16(&sq[slot][ti * 64 + off], qg + (size_t)(t0 + ti) * ROW + off);
    } else {
        int c = tid - 96; int si = c >> 3, off = (c & 7) * 4;
        cpasync16(&sv[slot][si * 32 + off], vg + (size_t)(s0 + si) * ROW + off);
    }
    if (tid == 0) cpasync16(&sb[slot][0], bg + s0);
    if (tid == 1) cpasync16(&sb[slot][4], dg + s0);
}

__device__ __forceinline__ void lds16(const float* p, float* r)
{
    float4 a = *(const float4*)(p + 0);
    float4 b = *(const float4*)(p + 4);
    float4 c = *(const float4*)(p + 8);
    float4 d = *(const float4*)(p + 12);
    r[0]=a.x; r[1]=a.y; r[2]=a.z; r[3]=a.w;
    r[4]=b.x; r[5]=b.y; r[6]=b.z; r[7]=b.w;
    r[8]=c.x; r[9]=c.y; r[10]=c.z; r[11]=c.w;
    r[12]=d.x; r[13]=d.y; r[14]=d.z; r[15]=d.w;
}

__global__ void __launch_bounds__(128) scan_kernel()
{
    __shared__ float sk[4][256];   // [slot][step_in_group*64 + row]
    __shared__ float sq[4][128];   // [slot][token_in_group*64 + row]
    __shared__ float sv[4][128];   // [slot][step_in_group*32 + vloc]
    __shared__ float sb[4][8];     // [slot][0..3]=beta  [4..7]=dec

    const int h = blockIdx.x >> 1;
    const int half = blockIdx.x & 1;
    const int tid = threadIdx.x;
    const int vloc = tid >> 2;
    const int j = tid & 3;
    const int v = (half << 5) + vloc;

    const float* kg = g_kbuf + h * 64;
    const float* qg = g_qbuf + h * 64;
    const float* vg = g_vbuf + h * 64 + half * 32;
    const float* bg = g_betab + h * SPAD;
    const float* dg = g_decb + h * SPAD;
    float* op = g_obuf + h * 64 + v;

    float S[16];
#pragma unroll
    for (int m = 0; m < 16; m++) S[m] = 0.f;

    scan_prefetch(0, tid, kg, qg, vg, bg, dg, sk, sq, sv, sb); CP_COMMIT();
    scan_prefetch(1, tid, kg, qg, vg, bg, dg, sk, sq, sv, sb); CP_COMMIT();
    CP_WAIT(1);
    __syncthreads();

    for (int g = 0; g < NGRP; g++) {
        scan_prefetch(g + 2, tid, kg, qg, vg, bg, dg, sk, sq, sv, sb);
        CP_COMMIT();

        const int slot = g & 3;
        float kc[16], qc[16];
        lds16(&sk[slot][j * 16], kc);

#pragma unroll
        for (int sp = 0; sp < 4; sp++) {
            const int s = g * 4 + sp;
            float kn[16];
            if (sp < 3) lds16(&sk[slot][(sp + 1) * 64 + j * 16], kn);
            if (!(sp & 1)) lds16(&sq[slot][(sp >> 1) * 64 + j * 16], qc);

            float vv = sv[slot][sp * 32 + vloc];
            float bb = sb[slot][sp];
            float dd = sb[slot][4 + sp];

            // pred = k . S  (4-way split to break FMA chain)
            float p0 = 0.f, p1 = 0.f, p2 = 0.f, p3 = 0.f;
#pragma unroll
            for (int m = 0; m < 4; m++) {
                p0 = fmaf(kc[m +  0], S[m +  0], p0);
                p1 = fmaf(kc[m +  4], S[m +  4], p1);
                p2 = fmaf(kc[m +  8], S[m +  8], p2);
                p3 = fmaf(kc[m + 12], S[m + 12], p3);
            }
            float pred = (p0 + p1) + (p2 + p3);
            pred += __shfl_xor_sync(0xffffffffu, pred, 1);
            pred += __shfl_xor_sync(0xffffffffu, pred, 2);

            float dv = (vv - dd * pred) * bb;
#pragma unroll
            for (int m = 0; m < 16; m++)
                S[m] = fmaf(S[m], dd, kc[m] * dv);

            if (sp & 1) {
                float o0 = 0.f, o1 = 0.f, o2 = 0.f, o3 = 0.f;
#pragma unroll
                for (int m = 0; m < 4; m++) {
                    o0 = fmaf(qc[m +  0], S[m +  0], o0);
                    o1 = fmaf(qc[m +  4], S[m +  4], o1);
                    o2 = fmaf(qc[m +  8], S[m +  8], o2);
                    o3 = fmaf(qc[m + 12], S[m + 12], o3);
                }
                float o = (o0 + o1) + (o2 + o3);
                o += __shfl_xor_sync(0xffffffffu, o, 1);
                o += __shfl_xor_sync(0xffffffffu, o, 2);
                if (j == 0) op[(size_t)(s >> 1) * ROW] = o;
            }

            if (sp < 3) {
#pragma unroll
                for (int m = 0; m < 16; m++) kc[m] = kn[m];
            }
        }

        CP_WAIT(1);
        __syncthreads();
    }
}

// ---------------------------------------------------------------------------
// Gated RMSNorm + swish gate, in-place on g_obuf. One warp per (t,h) row.
// ---------------------------------------------------------------------------
__global__ void post_kernel(const float* __restrict__ nw)
{
    int w = (blockIdx.x * blockDim.x + threadIdx.x) >> 5;
    int lane = threadIdx.x & 31;
    if (w >= T_ * H_) return;
    float* p = g_obuf + (size_t)w * 64;
    const float* gp = g_gbuf + (size_t)w * 64;
    float x0 = p[lane], x1 = p[lane + 32];
    float ss = x0 * x0 + x1 * x1;
#pragma unroll
    for (int o = 16; o; o >>= 1) ss += __shfl_xor_sync(0xffffffffu, ss, o);
    float rs = rsqrtf(ss * (1.0f / 64.0f) + 1e-5f);
    float g0 = gp[lane], g1 = gp[lane + 32];
    float w0 = nw[lane], w1 = nw[lane + 32];
    float sg0 = g0 / (1.0f + expf(-g0));
    float sg1 = g1 / (1.0f + expf(-g1));
    p[lane]      = x0 * rs * w0 * sg0;
    p[lane + 32] = x1 * rs * w1 * sg1;
}

// ---------------------------------------------------------------------------
// Host launcher
// ---------------------------------------------------------------------------
extern "C" void kernel_launch(void* const* d_in, const int* in_sizes, int n_in,
                              void* d_out, int out_size)
{
    const float* x       = (const float*)d_in[0];
    const float* Wq      = (const float*)d_in[1];
    const float* Wk      = (const float*)d_in[2];
    const float* Wv      = (const float*)d_in[3];
    const float* Wb      = (const float*)d_in[4];
    const float* Wa      = (const float*)d_in[5];
    const float* A_log   = (const float*)d_in[6];
    const float* dt_bias = (const float*)d_in[7];
    const float* Wg      = (const float*)d_in[8];
    const float* nw      = (const float*)d_in[9];
    const float* Wo      = (const float*)d_in[10];
    float* out = (float*)d_out;

    float *qb, *kb, *vb, *gb, *bb, *ab, *ob;
    cudaGetSymbolAddress((void**)&qb, g_qbuf);
    cudaGetSymbolAddress((void**)&kb, g_kbuf);
    cudaGetSymbolAddress((void**)&vb, g_vbuf);
    cudaGetSymbolAddress((void**)&gb, g_gbuf);
    cudaGetSymbolAddress((void**)&bb, g_bbuf);
    cudaGetSymbolAddress((void**)&ab, g_abuf);
    cudaGetSymbolAddress((void**)&ob, g_obuf);

    dim3 blk(256);
    // Projections
    sgemm_kernel<<<dim3(1024 / BN, T_ / BM), blk>>>(x, Wq, qb, T_, 1024, D_);
    sgemm_kernel<<<dim3(2048 / BN, T_ / BM), blk>>>(x, Wk, kb, T_, 2048, D_);
    sgemm_kernel<<<dim3(2048 / BN, T_ / BM), blk>>>(x, Wv, vb, T_, 2048, D_);
    sgemm_kernel<<<dim3(1024 / BN, T_ / BM), blk>>>(x, Wg, gb, T_, 1024, D_);
    sgemm_kernel<<<dim3(1,         T_ / BM), blk>>>(x, Wb, bb, T_, 32,   D_);
    sgemm_kernel<<<dim3(1,         T_ / BM), blk>>>(x, Wa, ab, T_, 16,   D_);

    // Pointwise prep
    {
        int warps = T_ * H_ + STEPS * H_;          // 98304
        prep_norm_kernel<<<(warps + 7) / 8, 256>>>();
        prep_scalar_kernel<<<(STEPS * H_) / 256, 256>>>(A_log, dt_bias);
    }

    // Sequential scan: 32 blocks (2 per head), 128 threads each
    scan_kernel<<<32, 128>>>();

    // Gated RMSNorm + swish
    post_kernel<<<(T_ * H_ + 7) / 8, 256>>>(nw);

    // Output projection
    sgemm_kernel<<<dim3(1024 / BN, T_ / BM), blk>>>(ob, Wo, out, T_, 1024, D_);
}

// round 4
// speedup vs baseline: 1.8473x; 1.0983x over previous
#include <cuda_runtime.h>
#include <cuda_bf16.h>
#include <math.h>

// ---------------------------------------------------------------------------
// Problem dims (fixed)
// ---------------------------------------------------------------------------
#define T_   2048
#define D_   1024
#define H_   16
#define HD_  64
#define NH_  2
#define STEPS (T_*NH_)          // 4096
#define ROW  (H_*HD_)           // 1024
#define SPAD (STEPS + 8)        // padded step count (prefetch overrun)
#define GSTEPS 8
#define NGRP8 (STEPS/GSTEPS)    // 512 groups of 8 steps

// ---------------------------------------------------------------------------
// Scratch (static device memory; allocation-free). Padded for the scan's
// cp.async prefetch which can read a few steps past the end (values unused).
// ---------------------------------------------------------------------------
__device__ __align__(256) float g_qbuf[(T_ + 4) * ROW];
__device__ __align__(256) float g_kbuf[SPAD * ROW];
__device__ __align__(256) float g_vbuf[SPAD * ROW];
__device__ __align__(256) float g_gbuf[T_ * ROW];
__device__ __align__(256) float g_bbuf[T_ * (NH_ * H_)];
__device__ __align__(256) float g_abuf[T_ * H_];
__device__ __align__(256) float g_betab[H_ * SPAD];     // transposed [h][s]
__device__ __align__(256) float g_decb[H_ * SPAD];      // transposed [h][s]
__device__ __align__(256) float g_obuf[T_ * ROW];

// ---------------------------------------------------------------------------
// f32x2 packed helpers (FFMA2 path: 2x fp32 throughput, PTX-only)
// ---------------------------------------------------------------------------
typedef unsigned long long ull;

__device__ __forceinline__ void fma2(ull& d, ull a, ull b) {
    asm("fma.rn.f32x2 %0, %1, %2, %3;" : "=l"(d) : "l"(a), "l"(b), "l"(d));
}
__device__ __forceinline__ ull pk2(float x, float y) {
    ull r;
    asm("mov.b64 %0, {%1, %2};" : "=l"(r)
        : "r"(__float_as_uint(x)), "r"(__float_as_uint(y)));
    return r;
}
__device__ __forceinline__ void up2(ull v, float& lo, float& hi) {
    unsigned a, b;
    asm("mov.b64 {%0, %1}, %2;" : "=r"(a), "=r"(b) : "l"(v));
    lo = __uint_as_float(a); hi = __uint_as_float(b);
}

// ---------------------------------------------------------------------------
// cp.async helpers (cpasync16 copies 16 BYTES = 4 floats)
// ---------------------------------------------------------------------------
__device__ __forceinline__ void cpasync16(void* dst, const void* src) {
    unsigned d = (unsigned)__cvta_generic_to_shared(dst);
    asm volatile("cp.async.cg.shared.global [%0], [%1], 16;" :: "r"(d), "l"(src));
}
#define CP_COMMIT() asm volatile("cp.async.commit_group;")
#define CP_WAIT(n)  asm volatile("cp.async.wait_group %0;" :: "n"(n))

// ---------------------------------------------------------------------------
// Big SGEMM: C[M,N] = A[M,K] @ B[K,N], row-major fp32, FFMA2.
// 128x128 tile, BK=16, 128 threads, 16x8 microtile (8 ull row-pairs x 8 cols).
// Requires M%128==0, N%128==0, K%16==0. Double-buffered (A: LDG->STS,
// B: cp.async).
// ---------------------------------------------------------------------------
#define GBK 16

__global__ void __launch_bounds__(128) sgemm_big_kernel(
    const float* __restrict__ A, const float* __restrict__ B,
    float* __restrict__ C, int M, int N, int K)
{
    __shared__ float As[2][GBK][128];   // [buf][k][row]
    __shared__ float Bs[2][GBK][128];   // [buf][k][col]

    const int tid = threadIdx.x;
    const int tx = tid & 15;            // 8 cols each
    const int ty = tid >> 4;            // 16 rows each
    const int rowC = blockIdx.y * 128;
    const int colC = blockIdx.x * 128;

    const float* Ap = A + (size_t)(rowC + tid) * K;            // one row / thread
    const float* Bp = B + (size_t)(tid >> 3) * N + colC + (tid & 7) * 16;

    ull acc[8][8];
#pragma unroll
    for (int r = 0; r < 8; r++)
#pragma unroll
        for (int c = 0; c < 8; c++) acc[r][c] = 0ull;

    const int nt = K / GBK;

    // prologue: fill buffer 0
    {
        float4 a0 = *(const float4*)(Ap + 0);
        float4 a1 = *(const float4*)(Ap + 4);
        float4 a2 = *(const float4*)(Ap + 8);
        float4 a3 = *(const float4*)(Ap + 12);
        As[0][0][tid] = a0.x;  As[0][1][tid] = a0.y;  As[0][2][tid] = a0.z;  As[0][3][tid] = a0.w;
        As[0][4][tid] = a1.x;  As[0][5][tid] = a1.y;  As[0][6][tid] = a1.z;  As[0][7][tid] = a1.w;
        As[0][8][tid] = a2.x;  As[0][9][tid] = a2.y;  As[0][10][tid] = a2.z; As[0][11][tid] = a2.w;
        As[0][12][tid] = a3.x; As[0][13][tid] = a3.y; As[0][14][tid] = a3.z; As[0][15][tid] = a3.w;
#pragma unroll
        for (int c = 0; c < 4; c++)
            cpasync16(&Bs[0][tid >> 3][(tid & 7) * 16 + c * 4], Bp + c * 4);
        CP_COMMIT();
        CP_WAIT(0);
    }
    __syncthreads();

    for (int t = 0; t < nt; t++) {
        const int cur = t & 1;
        const int nxt = cur ^ 1;

        if (t + 1 < nt) {
            const int k0 = (t + 1) * GBK;
            float4 a0 = *(const float4*)(Ap + k0 + 0);
            float4 a1 = *(const float4*)(Ap + k0 + 4);
            float4 a2 = *(const float4*)(Ap + k0 + 8);
            float4 a3 = *(const float4*)(Ap + k0 + 12);
            const float* bsrc = Bp + (size_t)k0 * N;
#pragma unroll
            for (int c = 0; c < 4; c++)
                cpasync16(&Bs[nxt][tid >> 3][(tid & 7) * 16 + c * 4], bsrc + c * 4);
            CP_COMMIT();
            As[nxt][0][tid] = a0.x;  As[nxt][1][tid] = a0.y;  As[nxt][2][tid] = a0.z;  As[nxt][3][tid] = a0.w;
            As[nxt][4][tid] = a1.x;  As[nxt][5][tid] = a1.y;  As[nxt][6][tid] = a1.z;  As[nxt][7][tid] = a1.w;
            As[nxt][8][tid] = a2.x;  As[nxt][9][tid] = a2.y;  As[nxt][10][tid] = a2.z; As[nxt][11][tid] = a2.w;
            As[nxt][12][tid] = a3.x; As[nxt][13][tid] = a3.y; As[nxt][14][tid] = a3.z; As[nxt][15][tid] = a3.w;
        } else {
            CP_COMMIT();
        }

#pragma unroll
        for (int kk = 0; kk < GBK; kk++) {
            ull a2r[8];
#pragma unroll
            for (int r = 0; r < 8; r++)
                a2r[r] = *(const ull*)&As[cur][kk][ty * 16 + 2 * r];
            float4 b0 = *(const float4*)&Bs[cur][kk][tx * 8];
            float4 b1 = *(const float4*)&Bs[cur][kk][tx * 8 + 4];
            ull b2[8];
            b2[0] = pk2(b0.x, b0.x); b2[1] = pk2(b0.y, b0.y);
            b2[2] = pk2(b0.z, b0.z); b2[3] = pk2(b0.w, b0.w);
            b2[4] = pk2(b1.x, b1.x); b2[5] = pk2(b1.y, b1.y);
            b2[6] = pk2(b1.z, b1.z); b2[7] = pk2(b1.w, b1.w);
#pragma unroll
            for (int r = 0; r < 8; r++)
#pragma unroll
                for (int c = 0; c < 8; c++)
                    fma2(acc[r][c], a2r[r], b2[c]);
        }

        CP_WAIT(0);
        __syncthreads();
    }

    // epilogue: store 16x8 microtile
#pragma unroll
    for (int r = 0; r < 8; r++) {
        float lo[8], hi[8];
#pragma unroll
        for (int c = 0; c < 8; c++) up2(acc[r][c], lo[c], hi[c]);
        int row0 = rowC + ty * 16 + 2 * r;
        float* c0 = C + (size_t)row0 * N + colC + tx * 8;
        float* c1 = c0 + N;
        *(float4*)(c0 + 0) = make_float4(lo[0], lo[1], lo[2], lo[3]);
        *(float4*)(c0 + 4) = make_float4(lo[4], lo[5], lo[6], lo[7]);
        *(float4*)(c1 + 0) = make_float4(hi[0], hi[1], hi[2], hi[3]);
        *(float4*)(c1 + 4) = make_float4(hi[4], hi[5], hi[6], hi[7]);
    }
}

// ---------------------------------------------------------------------------
// Small SGEMM (N=16/32): 128x64 tile, BK=16, 256 threads (from R2).
// ---------------------------------------------------------------------------
#define BM 128
#define BN 64
#define BK 16

__global__ void __launch_bounds__(256) sgemm_kernel(
    const float* __restrict__ A, const float* __restrict__ B,
    float* __restrict__ C, int M, int N, int K)
{
    __shared__ float As[BK][BM + 4];
    __shared__ float Bs[BK][BN];

    const int tid = threadIdx.x;
    const int tx = tid & 15;
    const int ty = tid >> 4;
    const int rowC = blockIdx.y * BM;
    const int colC = blockIdx.x * BN;

    const int rowA = tid >> 2;
    const int kA   = (tid & 3) * 4;
    const int rowB = tid >> 4;
    const int colB = (tid & 15) * 4;

    ull acc2[4][4];
#pragma unroll
    for (int r = 0; r < 4; r++)
#pragma unroll
        for (int jj = 0; jj < 4; jj++) acc2[r][jj] = 0ull;

    for (int k0 = 0; k0 < K; k0 += BK) {
#pragma unroll
        for (int r = 0; r < 2; r++) {
            int row = rowA + r * 64;
            float4 a = *(const float4*)(A + (size_t)(rowC + row) * K + k0 + kA);
            As[kA + 0][row] = a.x; As[kA + 1][row] = a.y;
            As[kA + 2][row] = a.z; As[kA + 3][row] = a.w;
        }
        {
            float4 bv = make_float4(0.f, 0.f, 0.f, 0.f);
            if (colC + colB < N)
                bv = *(const float4*)(B + (size_t)(k0 + rowB) * N + colC + colB);
            Bs[rowB][colB + 0] = bv.x; Bs[rowB][colB + 1] = bv.y;
            Bs[rowB][colB + 2] = bv.z; Bs[rowB][colB + 3] = bv.w;
        }
        __syncthreads();

#pragma unroll
        for (int kk = 0; kk < BK; kk++) {
            float4 b0 = *(const float4*)&Bs[kk][tx * 4];
            ull b2[4];
            b2[0] = pk2(b0.x, b0.x); b2[1] = pk2(b0.y, b0.y);
            b2[2] = pk2(b0.z, b0.z); b2[3] = pk2(b0.w, b0.w);
            ull a2[4];
#pragma unroll
            for (int r = 0; r < 4; r++)
                a2[r] = *(const ull*)&As[kk][ty * 8 + 2 * r];
#pragma unroll
            for (int r = 0; r < 4; r++)
#pragma unroll
                for (int jj = 0; jj < 4; jj++)
                    fma2(acc2[r][jj], a2[r], b2[jj]);
        }
        __syncthreads();
    }

    if (colC + tx * 4 < N) {
#pragma unroll
        for (int r = 0; r < 4; r++) {
            float lo[4], hi[4];
#pragma unroll
            for (int jj = 0; jj < 4; jj++) up2(acc2[r][jj], lo[jj], hi[jj]);
            int row0 = rowC + ty * 8 + 2 * r;
            *(float4*)(C + (size_t)row0 * N + colC + tx * 4) =
                make_float4(lo[0], lo[1], lo[2], lo[3]);
            *(float4*)(C + (size_t)(row0 + 1) * N + colC + tx * 4) =
                make_float4(hi[0], hi[1], hi[2], hi[3]);
        }
    }
}

// ---------------------------------------------------------------------------
// l2norm rows of 64 (q: scale by HD^-0.5; k: no scale). One warp per row.
// ---------------------------------------------------------------------------
__global__ void prep_norm_kernel()
{
    const int TQ = T_ * H_;
    const int TK = STEPS * H_;
    int w = (blockIdx.x * blockDim.x + threadIdx.x) >> 5;
    int lane = threadIdx.x & 31;
    if (w >= TQ + TK) return;
    float* p;
    float scl;
    if (w < TQ) { p = g_qbuf + (size_t)w * 64; scl = 0.125f; }
    else        { p = g_kbuf + (size_t)(w - TQ) * 64; scl = 1.0f; }
    float x0 = p[lane], x1 = p[lane + 32];
    float ss = x0 * x0 + x1 * x1;
#pragma unroll
    for (int o = 16; o; o >>= 1) ss += __shfl_xor_sync(0xffffffffu, ss, o);
    float rs = rsqrtf(ss + 1e-6f) * scl;
    p[lane] = x0 * rs;
    p[lane + 32] = x1 * rs;
}

// ---------------------------------------------------------------------------
// beta/dec precompute, written TRANSPOSED [h][s] for contiguous cp.async.
// ---------------------------------------------------------------------------
__global__ void prep_scalar_kernel(const float* __restrict__ A_log,
                                   const float* __restrict__ dt_bias)
{
    int i = blockIdx.x * blockDim.x + threadIdx.x;
    if (i >= STEPS * H_) return;
    int h = i & 15;
    int nh = (i >> 4) & 1;
    int t = i >> 5;
    int s = t * 2 + nh;
    float br = g_bbuf[i];
    g_betab[h * SPAD + s] = 2.0f / (1.0f + expf(-br));
    float d = 1.0f;
    if (nh == 0) {
        float a = g_abuf[t * H_ + h] + dt_bias[h];
        float sp = (a > 20.0f) ? a : log1pf(expf(a));
        d = expf(-expf(A_log[h]) * sp);
    }
    g_decb[h * SPAD + s] = d;
}

// ---------------------------------------------------------------------------
// Scan: cp.async smem ring, groups of 8 steps, 4 slots, lookahead 3 groups.
// Chunk accounting (cpasync16 = 16 BYTES = 4 floats):
//   k: 8 steps x 64 fl = 128 chunks -> all 128 threads
//   q: 4 tokens x 64 fl = 64 chunks -> tids 0..63
//   v: 8 steps x 32 fl  = 64 chunks -> tids 64..127
//   beta/dec: 2+2 chunks -> tids 0..3
// ---------------------------------------------------------------------------
__device__ __forceinline__ void scan_prefetch(
    int gi, int tid,
    const float* kg, const float* qg, const float* vg,
    const float* bg, const float* dg,
    float (*sk)[GSTEPS*64], float (*sq)[(GSTEPS/2)*64],
    float (*sv)[GSTEPS*32], float (*sb)[16])
{
    int slot = gi & 3;
    int s0 = gi * GSTEPS; if (s0 > STEPS) s0 = STEPS;
    int t0 = s0 >> 1;
    {   // k
        int si = tid >> 4, off = (tid & 15) * 4;
        cpasync16(&sk[slot][si * 64 + off], kg + (size_t)(s0 + si) * ROW + off);
    }
    if (tid < 64) {   // q
        int ti = tid >> 4, off = (tid & 15) * 4;
        cpasync16(&sq[slot][ti * 64 + off], qg + (size_t)(t0 + ti) * ROW + off);
    } else {          // v
        int c = tid - 64; int si = c >> 3, off = (c & 7) * 4;
        cpasync16(&sv[slot][si * 32 + off], vg + (size_t)(s0 + si) * ROW + off);
    }
    if (tid < 2)      cpasync16(&sb[slot][tid * 4], bg + s0 + tid * 4);
    else if (tid < 4) cpasync16(&sb[slot][8 + (tid - 2) * 4], dg + s0 + (tid - 2) * 4);
}

__device__ __forceinline__ void lds16(const float* p, float* r)
{
    float4 a = *(const float4*)(p + 0);
    float4 b = *(const float4*)(p + 4);
    float4 c = *(const float4*)(p + 8);
    float4 d = *(const float4*)(p + 12);
    r[0]=a.x; r[1]=a.y; r[2]=a.z; r[3]=a.w;
    r[4]=b.x; r[5]=b.y; r[6]=b.z; r[7]=b.w;
    r[8]=c.x; r[9]=c.y; r[10]=c.z; r[11]=c.w;
    r[12]=d.x; r[13]=d.y; r[14]=d.z; r[15]=d.w;
}

__global__ void __launch_bounds__(128) scan_kernel()
{
    __shared__ float sk[4][GSTEPS*64];
    __shared__ float sq[4][(GSTEPS/2)*64];
    __shared__ float sv[4][GSTEPS*32];
    __shared__ float sb[4][16];           // [0..7]=beta, [8..15]=dec

    const int h = blockIdx.x >> 1;
    const int half = blockIdx.x & 1;
    const int tid = threadIdx.x;
    const int vloc = tid >> 2;
    const int j = tid & 3;
    const int v = (half << 5) + vloc;

    const float* kg = g_kbuf + h * 64;
    const float* qg = g_qbuf + h * 64;
    const float* vg = g_vbuf + h * 64 + half * 32;
    const float* bg = g_betab + h * SPAD;
    const float* dg = g_decb + h * SPAD;
    float* op = g_obuf + h * 64 + v;

    float S[16];
#pragma unroll
    for (int m = 0; m < 16; m++) S[m] = 0.f;

    scan_prefetch(0, tid, kg, qg, vg, bg, dg, sk, sq, sv, sb); CP_COMMIT();
    scan_prefetch(1, tid, kg, qg, vg, bg, dg, sk, sq, sv, sb); CP_COMMIT();
    scan_prefetch(2, tid, kg, qg, vg, bg, dg, sk, sq, sv, sb); CP_COMMIT();
    CP_WAIT(2);
    __syncthreads();

    for (int g = 0; g < NGRP8; g++) {
        scan_prefetch(g + 3, tid, kg, qg, vg, bg, dg, sk, sq, sv, sb);
        CP_COMMIT();

        const int slot = g & 3;
        float kc[16], qc[16];
        lds16(&sk[slot][j * 16], kc);

#pragma unroll
        for (int sp = 0; sp < GSTEPS; sp++) {
            const int s = g * GSTEPS + sp;
            float kn[16];
            if (sp < GSTEPS - 1) lds16(&sk[slot][(sp + 1) * 64 + j * 16], kn);
            if (!(sp & 1)) lds16(&sq[slot][(sp >> 1) * 64 + j * 16], qc);

            float vv = sv[slot][sp * 32 + vloc];
            float bb = sb[slot][sp];
            float dd = sb[slot][8 + sp];

            // pred = k . S  (4-way split to break FMA chain)
            float p0 = 0.f, p1 = 0.f, p2 = 0.f, p3 = 0.f;
#pragma unroll
            for (int m = 0; m < 4; m++) {
                p0 = fmaf(kc[m +  0], S[m +  0], p0);
                p1 = fmaf(kc[m +  4], S[m +  4], p1);
                p2 = fmaf(kc[m +  8], S[m +  8], p2);
                p3 = fmaf(kc[m + 12], S[m + 12], p3);
            }
            float pred = (p0 + p1) + (p2 + p3);
            pred += __shfl_xor_sync(0xffffffffu, pred, 1);
            pred += __shfl_xor_sync(0xffffffffu, pred, 2);

            float dv = (vv - dd * pred) * bb;
#pragma unroll
            for (int m = 0; m < 16; m++)
                S[m] = fmaf(S[m], dd, kc[m] * dv);

            if (sp & 1) {
                float o0 = 0.f, o1 = 0.f, o2 = 0.f, o3 = 0.f;
#pragma unroll
                for (int m = 0; m < 4; m++) {
                    o0 = fmaf(qc[m +  0], S[m +  0], o0);
                    o1 = fmaf(qc[m +  4], S[m +  4], o1);
                    o2 = fmaf(qc[m +  8], S[m +  8], o2);
                    o3 = fmaf(qc[m + 12], S[m + 12], o3);
                }
                float o = (o0 + o1) + (o2 + o3);
                o += __shfl_xor_sync(0xffffffffu, o, 1);
                o += __shfl_xor_sync(0xffffffffu, o, 2);
                if (j == 0) op[(size_t)(s >> 1) * ROW] = o;
            }

            if (sp < GSTEPS - 1) {
#pragma unroll
                for (int m = 0; m < 16; m++) kc[m] = kn[m];
            }
        }

        CP_WAIT(2);
        __syncthreads();
    }
}

// ---------------------------------------------------------------------------
// Gated RMSNorm + swish gate, in-place on g_obuf. One warp per (t,h) row.
// ---------------------------------------------------------------------------
__global__ void post_kernel(const float* __restrict__ nw)
{
    int w = (blockIdx.x * blockDim.x + threadIdx.x) >> 5;
    int lane = threadIdx.x & 31;
    if (w >= T_ * H_) return;
    float* p = g_obuf + (size_t)w * 64;
    const float* gp = g_gbuf + (size_t)w * 64;
    float x0 = p[lane], x1 = p[lane + 32];
    float ss = x0 * x0 + x1 * x1;
#pragma unroll
    for (int o = 16; o; o >>= 1) ss += __shfl_xor_sync(0xffffffffu, ss, o);
    float rs = rsqrtf(ss * (1.0f / 64.0f) + 1e-5f);
    float g0 = gp[lane], g1 = gp[lane + 32];
    float w0 = nw[lane], w1 = nw[lane + 32];
    float sg0 = g0 / (1.0f + expf(-g0));
    float sg1 = g1 / (1.0f + expf(-g1));
    p[lane]      = x0 * rs * w0 * sg0;
    p[lane + 32] = x1 * rs * w1 * sg1;
}

// ---------------------------------------------------------------------------
// Host launcher
// ---------------------------------------------------------------------------
extern "C" void kernel_launch(void* const* d_in, const int* in_sizes, int n_in,
                              void* d_out, int out_size)
{
    const float* x       = (const float*)d_in[0];
    const float* Wq      = (const float*)d_in[1];
    const float* Wk      = (const float*)d_in[2];
    const float* Wv      = (const float*)d_in[3];
    const float* Wb      = (const float*)d_in[4];
    const float* Wa      = (const float*)d_in[5];
    const float* A_log   = (const float*)d_in[6];
    const float* dt_bias = (const float*)d_in[7];
    const float* Wg      = (const float*)d_in[8];
    const float* nw      = (const float*)d_in[9];
    const float* Wo      = (const float*)d_in[10];
    float* out = (float*)d_out;

    float *qb, *kb, *vb, *gb, *bb, *ab, *ob;
    cudaGetSymbolAddress((void**)&qb, g_qbuf);
    cudaGetSymbolAddress((void**)&kb, g_kbuf);
    cudaGetSymbolAddress((void**)&vb, g_vbuf);
    cudaGetSymbolAddress((void**)&gb, g_gbuf);
    cudaGetSymbolAddress((void**)&bb, g_bbuf);
    cudaGetSymbolAddress((void**)&ab, g_abuf);
    cudaGetSymbolAddress((void**)&ob, g_obuf);

    // Projections (big GEMMs: 128x128 tiles, 128 threads)
    sgemm_big_kernel<<<dim3(1024 / 128, T_ / 128), 128>>>(x, Wq, qb, T_, 1024, D_);
    sgemm_big_kernel<<<dim3(2048 / 128, T_ / 128), 128>>>(x, Wk, kb, T_, 2048, D_);
    sgemm_big_kernel<<<dim3(2048 / 128, T_ / 128), 128>>>(x, Wv, vb, T_, 2048, D_);
    sgemm_big_kernel<<<dim3(1024 / 128, T_ / 128), 128>>>(x, Wg, gb, T_, 1024, D_);
    // Small projections
    sgemm_kernel<<<dim3(1, T_ / BM), 256>>>(x, Wb, bb, T_, 32, D_);
    sgemm_kernel<<<dim3(1, T_ / BM), 256>>>(x, Wa, ab, T_, 16, D_);

    // Pointwise prep
    {
        int warps = T_ * H_ + STEPS * H_;
        prep_norm_kernel<<<(warps + 7) / 8, 256>>>();
        prep_scalar_kernel<<<(STEPS * H_) / 256, 256>>>(A_log, dt_bias);
    }

    // Sequential scan: 32 blocks (2 per head), 128 threads each
    scan_kernel<<<32, 128>>>();

    // Gated RMSNorm + swish
    post_kernel<<<(T_ * H_ + 7) / 8, 256>>>(nw);

    // Output projection
    sgemm_big_kernel<<<dim3(1024 / 128, T_ / 128), 128>>>(ob, Wo, out, T_, 1024, D_);
}